// round 1
// baseline (speedup 1.0000x reference)
#include <cuda_runtime.h>
#include <math.h>

// Problem constants
#define BN   32768
#define DN   512
#define EN   16
#define TK   4
#define TT   3
#define H1N  16
#define H2N  8
#define ON   16

// Tiling
#define ROWS     64     // rows per CTA
#define KC       32     // K chunk
#define NTHREADS 512
#define NCOLS    320    // 256 (h1) + 48 (logits) + 16 zero pad

// Shared memory float offsets (single dynamic allocation, phases alias)
#define XS_OFF   0        // 64*33   = 2112   (GEMM phase)
#define WS_OFF   2112     // 32*320  = 10240  (GEMM phase)  -> GEMM region ends at 12352
#define H1_OFF   0        // 64*273  = 17472  (epilogue, aliases GEMM region)
#define LG_OFF   17472    // 64*49   = 3136
#define B1_OFF   20608    // 256
#define W2_OFF   20864    // 16*130  = 2080
#define W3_OFF   22944    // 16*130  = 2080
#define B2_OFF   25024    // 16*9    = 144
#define B3_OFF   25168    // 16*17   = 272
#define BG_OFF   25440    // 48
#define IMP_OFF  25488    // 48
#define LOAD_OFF 25536    // 48
#define LSE_OFF  25584    // 64
#define SMEM_FLOATS 25648 // 102592 bytes

__device__ float g_imp[TT * EN];
__device__ float g_load[TT * EN];
__device__ float g_rz;

__device__ __forceinline__ unsigned long long bcast2(float v) {
    unsigned long long r;
    unsigned u = __float_as_uint(v);
    asm("mov.b64 %0, {%1, %1};" : "=l"(r) : "r"(u));
    return r;
}

__device__ __forceinline__ void fma2(unsigned long long& d, unsigned long long a,
                                     unsigned long long b) {
    asm("fma.rn.f32x2 %0, %1, %2, %0;" : "+l"(d) : "l"(a), "l"(b));
}

__device__ __forceinline__ void unpack2(unsigned long long v, float& lo, float& hi) {
    asm("mov.b64 {%0, %1}, %2;" : "=f"(lo), "=f"(hi) : "l"(v));
}

__global__ void moe_init_kernel() {
    int i = threadIdx.x;
    if (i < TT * EN) { g_imp[i] = 0.f; g_load[i] = 0.f; }
    if (i == 0) g_rz = 0.f;
}

extern __shared__ float sm[];

__global__ __launch_bounds__(NTHREADS, 1)
void moe_main_kernel(const float* __restrict__ x,
                     const float* __restrict__ wgates,
                     const float* __restrict__ bgates,
                     const float* __restrict__ W1,
                     const float* __restrict__ b1,
                     const float* __restrict__ W2,
                     const float* __restrict__ b2,
                     const float* __restrict__ W3,
                     const float* __restrict__ b3,
                     float* __restrict__ out) {
    const int tid  = threadIdx.x;
    const int row0 = blockIdx.x * ROWS;
    const int tx   = tid & 31;   // column group
    const int ty   = tid >> 5;   // row group (0..15)
    const int rbase = ty * 4;

    // ---- Stage small persistent weights into padded (conflict-free) smem ----
    for (int i = tid; i < 256; i += NTHREADS) sm[B1_OFF + i] = b1[i];
    for (int i = tid; i < 2048; i += NTHREADS) {
        sm[W2_OFF + (i >> 7) * 130 + (i & 127)] = W2[i];
        sm[W3_OFF + (i >> 7) * 130 + (i & 127)] = W3[i];
    }
    for (int i = tid; i < 128; i += NTHREADS) sm[B2_OFF + (i >> 3) * 9 + (i & 7)] = b2[i];
    for (int i = tid; i < 256; i += NTHREADS) sm[B3_OFF + (i >> 4) * 17 + (i & 15)] = b3[i];
    if (tid < 48) {
        sm[BG_OFF + tid] = bgates[tid];
        sm[IMP_OFF + tid] = 0.f;
        sm[LOAD_OFF + tid] = 0.f;
    }

    // ---- GEMM accumulators: 4 rows x 5 f32x2 column pairs ----
    unsigned long long acc[4][5];
#pragma unroll
    for (int i = 0; i < 4; i++)
#pragma unroll
        for (int j = 0; j < 5; j++) acc[i][j] = 0ull;

    // online logsumexp state (threads 0..63, one row each)
    float lm = -INFINITY, ls = 0.f;

    for (int kc = 0; kc < DN / KC; ++kc) {
        // stage x tile: xs[r][kk], row stride 33 (conflict-free row scans)
        {
            int r = tid >> 3, q = tid & 7;
            float4 v = *(const float4*)(x + (size_t)(row0 + r) * DN + kc * KC + q * 4);
            float* xp = &sm[XS_OFF + r * 33 + q * 4];
            xp[0] = v.x; xp[1] = v.y; xp[2] = v.z; xp[3] = v.w;
        }
        // stage W tile: ws[kk][n], n<256 -> W1[e=n/16, d, h=n%16]; n<304 -> gates
#pragma unroll
        for (int it = 0; it < (KC * NCOLS) / NTHREADS; ++it) {
            int idx = tid + it * NTHREADS;
            int kk = idx / NCOLS;
            int n = idx - kk * NCOLS;
            int d = kc * KC + kk;
            float w;
            if (n < 256) {
                w = W1[(n >> 4) * (DN * H1N) + d * 16 + (n & 15)];
            } else if (n < 304) {
                int m = n - 256;
                w = wgates[(m >> 4) * (DN * EN) + d * 16 + (m & 15)];
            } else {
                w = 0.f;
            }
            sm[WS_OFF + kk * NCOLS + n] = w;
        }
        __syncthreads();

        // logsumexp update (row-per-thread over this chunk)
        if (tid < ROWS) {
            const float* xr = &sm[XS_OFF + tid * 33];
            float cm = xr[0];
#pragma unroll
            for (int kk = 1; kk < KC; ++kk) cm = fmaxf(cm, xr[kk]);
            float nm = fmaxf(lm, cm);
            ls *= __expf(lm - nm);
            float add = 0.f;
#pragma unroll
            for (int kk = 0; kk < KC; ++kk) add += __expf(xr[kk] - nm);
            ls += add;
            lm = nm;
        }

        // f32x2 outer-product GEMM
#pragma unroll 4
        for (int kk = 0; kk < KC; ++kk) {
            unsigned long long a2[4];
#pragma unroll
            for (int i = 0; i < 4; i++) a2[i] = bcast2(sm[XS_OFF + (rbase + i) * 33 + kk]);
#pragma unroll
            for (int j = 0; j < 5; j++) {
                unsigned long long bb =
                    *(const unsigned long long*)&sm[WS_OFF + kk * NCOLS + 2 * (tx + 32 * j)];
#pragma unroll
                for (int i = 0; i < 4; i++) fma2(acc[i][j], a2[i], bb);
            }
        }
        __syncthreads();
    }

    // ---- write accumulators into padded epilogue smem (h1 with bias+relu, logits) ----
#pragma unroll
    for (int j = 0; j < 5; j++) {
        int c = 2 * (tx + 32 * j);
#pragma unroll
        for (int i = 0; i < 4; i++) {
            int row = rbase + i;
            float vx, vy;
            unpack2(acc[i][j], vx, vy);
            if (c < 256) {
                int e = c >> 4, h = c & 15;  // c even -> h<=14, pair stays in-expert
                sm[H1_OFF + row * 273 + e * 17 + h]     = fmaxf(vx + sm[B1_OFF + c], 0.f);
                sm[H1_OFF + row * 273 + e * 17 + h + 1] = fmaxf(vy + sm[B1_OFF + c + 1], 0.f);
            } else if (c < 304) {
                int m = c - 256;
                sm[LG_OFF + row * 49 + m]     = vx + sm[BG_OFF + m];
                sm[LG_OFF + row * 49 + m + 1] = vy + sm[BG_OFF + m + 1];
            }
        }
    }
    if (tid < ROWS) sm[LSE_OFF + tid] = lm + __logf(ls);
    __syncthreads();

    if (tid == 0) {
        float s = 0.f;
        for (int r = 0; r < ROWS; r++) s += sm[LSE_OFF + r];
        atomicAdd(&g_rz, s);
    }

    // ---- gating + sparse expert layers 2/3: one thread per (task,row) ----
    if (tid < ROWS * TT) {
        int t = tid / ROWS;
        int row = tid - t * ROWS;
        float l[16];
#pragma unroll
        for (int e = 0; e < 16; e++) l[e] = sm[LG_OFF + row * 49 + t * 16 + e];
        int sel[4];
        float sv[4];
#pragma unroll
        for (int k = 0; k < 4; k++) {
            float best = -INFINITY;
            int bi = 0;
#pragma unroll
            for (int e = 0; e < 16; e++)
                if (l[e] > best) { best = l[e]; bi = e; }
            sv[k] = best;
            sel[k] = bi;
            l[bi] = -INFINITY;
        }
        float m = sv[0];
        float g[4], ssum = 0.f;
#pragma unroll
        for (int k = 0; k < 4; k++) { g[k] = __expf(sv[k] - m); ssum += g[k]; }
        float inv = 1.f / ssum;

        float y[16];
#pragma unroll
        for (int o = 0; o < 16; o++) y[o] = 0.f;

#pragma unroll
        for (int k = 0; k < 4; k++) {
            int e = sel[k];
            float gk = g[k] * inv;
            float h[16];
#pragma unroll
            for (int i = 0; i < 16; i++) h[i] = sm[H1_OFF + row * 273 + e * 17 + i];
            float h2v[8];
#pragma unroll
            for (int j = 0; j < 8; j++) {
                float a = sm[B2_OFF + e * 9 + j];
#pragma unroll
                for (int i = 0; i < 16; i++) a += h[i] * sm[W2_OFF + e * 130 + i * 8 + j];
                h2v[j] = fmaxf(a, 0.f);
            }
#pragma unroll
            for (int o = 0; o < 16; o++) {
                float a = sm[B3_OFF + e * 17 + o];
#pragma unroll
                for (int j = 0; j < 8; j++) a += h2v[j] * sm[W3_OFF + e * 130 + j * 16 + o];
                y[o] += gk * fmaxf(a, 0.f);
            }
            atomicAdd(&sm[IMP_OFF + t * 16 + e], gk);
            atomicAdd(&sm[LOAD_OFF + t * 16 + e], 1.f);
        }
        float* yo = out + (size_t)t * BN * ON + (size_t)(row0 + row) * ON;
#pragma unroll
        for (int o = 0; o < 16; o++) yo[o] = y[o];
    }
    __syncthreads();

    // flush per-CTA loss partials
    if (tid < 48) atomicAdd(&g_imp[tid], sm[IMP_OFF + tid]);
    else if (tid < 96) atomicAdd(&g_load[tid - 48], sm[LOAD_OFF + tid - 48]);
}

__global__ void moe_finalize_kernel(float* __restrict__ out, int out_size) {
    if (threadIdx.x != 0 || blockIdx.x != 0) return;
    float lb = 0.f;
    for (int t = 0; t < TT; t++) {
        float imp[16], ld[16];
        float si = 0.f, sl = 0.f, sil = 0.f;
        for (int e = 0; e < 16; e++) {
            imp[e] = g_imp[t * 16 + e];
            ld[e]  = g_load[t * 16 + e];
            si += imp[e]; sl += ld[e]; sil += imp[e] * ld[e];
        }
        float mi = si / 16.f, ml = sl / 16.f;
        float vi = 0.f, vl = 0.f;
        for (int e = 0; e < 16; e++) {
            float di = imp[e] - mi, dl = ld[e] - ml;
            vi += di * di; vl += dl * dl;
        }
        vi /= 15.f;  // ddof=1
        vl /= 15.f;
        float cvi = vi / (mi * mi + 1e-10f);
        float cvl = vl / (ml * ml + 1e-10f);
        lb += 0.01f * (cvi + cvl) + 0.01f * 16.f * sil / (float)BN;
    }
    size_t base = (size_t)TT * BN * ON;
    if (out_size > (int)base)     out[base]     = lb;
    if (out_size > (int)base + 1) out[base + 1] = 3.f * 0.001f * g_rz / (float)BN;
}

extern "C" void kernel_launch(void* const* d_in, const int* in_sizes, int n_in,
                              void* d_out, int out_size) {
    const float* x      = (const float*)d_in[0];
    const float* wgates = (const float*)d_in[1];
    const float* bgates = (const float*)d_in[2];
    const float* W1     = (const float*)d_in[3];
    const float* b1     = (const float*)d_in[4];
    const float* W2     = (const float*)d_in[5];
    const float* b2     = (const float*)d_in[6];
    const float* W3     = (const float*)d_in[7];
    const float* b3     = (const float*)d_in[8];
    float* out = (float*)d_out;

    cudaFuncSetAttribute(moe_main_kernel, cudaFuncAttributeMaxDynamicSharedMemorySize,
                         SMEM_FLOATS * sizeof(float));

    moe_init_kernel<<<1, 64>>>();
    moe_main_kernel<<<BN / ROWS, NTHREADS, SMEM_FLOATS * sizeof(float)>>>(
        x, wgates, bgates, W1, b1, W2, b2, W3, b3, out);
    moe_finalize_kernel<<<1, 32>>>(out, out_size);
}

// round 2
// speedup vs baseline: 1.0005x; 1.0005x over previous
#include <cuda_runtime.h>
#include <math.h>

// Problem constants
#define BN   32768
#define DN   512
#define EN   16
#define TK   4
#define TT   3
#define H1N  16
#define H2N  8
#define ON   16

// Tiling
#define ROWS     64     // rows per CTA
#define KC       32     // K chunk
#define NTHREADS 512
#define NCOLS    320    // 256 (h1) + 48 (logits) + 16 zero pad

// Shared memory float offsets (single dynamic allocation, phases alias)
#define XS_OFF   0        // 64*33   = 2112   (GEMM phase)
#define WS_OFF   2112     // 32*320  = 10240  (GEMM phase)  -> GEMM region ends at 12352
#define H1_OFF   0        // 64*273  = 17472  (epilogue, aliases GEMM region)
#define LG_OFF   17472    // 64*49   = 3136
#define B1_OFF   20608    // 256
#define W2_OFF   20864    // 16*130  = 2080
#define W3_OFF   22944    // 16*130  = 2080
#define B2_OFF   25024    // 16*9    = 144
#define B3_OFF   25168    // 16*17   = 272
#define BG_OFF   25440    // 48
#define IMP_OFF  25488    // 48
#define LOAD_OFF 25536    // 48
#define LSE_OFF  25584    // 64
#define SMEM_FLOATS 25648 // 102592 bytes

__device__ float g_imp[TT * EN];
__device__ float g_load[TT * EN];
__device__ float g_rz;

__device__ __forceinline__ unsigned long long bcast2(float v) {
    unsigned long long r;
    unsigned u = __float_as_uint(v);
    asm("mov.b64 %0, {%1, %1};" : "=l"(r) : "r"(u));
    return r;
}

__device__ __forceinline__ void fma2(unsigned long long& d, unsigned long long a,
                                     unsigned long long b) {
    asm("fma.rn.f32x2 %0, %1, %2, %0;" : "+l"(d) : "l"(a), "l"(b));
}

__device__ __forceinline__ void unpack2(unsigned long long v, float& lo, float& hi) {
    asm("mov.b64 {%0, %1}, %2;" : "=f"(lo), "=f"(hi) : "l"(v));
}

__global__ void moe_init_kernel() {
    int i = threadIdx.x;
    if (i < TT * EN) { g_imp[i] = 0.f; g_load[i] = 0.f; }
    if (i == 0) g_rz = 0.f;
}

extern __shared__ float sm[];

__global__ __launch_bounds__(NTHREADS, 1)
void moe_main_kernel(const float* __restrict__ x,
                     const float* __restrict__ wgates,
                     const float* __restrict__ bgates,
                     const float* __restrict__ W1,
                     const float* __restrict__ b1,
                     const float* __restrict__ W2,
                     const float* __restrict__ b2,
                     const float* __restrict__ W3,
                     const float* __restrict__ b3,
                     float* __restrict__ out) {
    const int tid  = threadIdx.x;
    const int row0 = blockIdx.x * ROWS;
    const int tx   = tid & 31;   // column group
    const int ty   = tid >> 5;   // row group (0..15)
    const int rbase = ty * 4;

    // ---- Stage small persistent weights into padded (conflict-free) smem ----
    for (int i = tid; i < 256; i += NTHREADS) sm[B1_OFF + i] = b1[i];
    for (int i = tid; i < 2048; i += NTHREADS) {
        sm[W2_OFF + (i >> 7) * 130 + (i & 127)] = W2[i];
        sm[W3_OFF + (i >> 7) * 130 + (i & 127)] = W3[i];
    }
    for (int i = tid; i < 128; i += NTHREADS) sm[B2_OFF + (i >> 3) * 9 + (i & 7)] = b2[i];
    for (int i = tid; i < 256; i += NTHREADS) sm[B3_OFF + (i >> 4) * 17 + (i & 15)] = b3[i];
    if (tid < 48) {
        sm[BG_OFF + tid] = bgates[tid];
        sm[IMP_OFF + tid] = 0.f;
        sm[LOAD_OFF + tid] = 0.f;
    }

    // ---- GEMM accumulators: 4 rows x 5 f32x2 column pairs ----
    unsigned long long acc[4][5];
#pragma unroll
    for (int i = 0; i < 4; i++)
#pragma unroll
        for (int j = 0; j < 5; j++) acc[i][j] = 0ull;

    // online logsumexp state (threads 0..63, one row each)
    float lm = -INFINITY, ls = 0.f;

    for (int kc = 0; kc < DN / KC; ++kc) {
        // stage x tile: xs[r][kk], row stride 33 (conflict-free row scans)
        {
            int r = tid >> 3, q = tid & 7;
            float4 v = *(const float4*)(x + (size_t)(row0 + r) * DN + kc * KC + q * 4);
            float* xp = &sm[XS_OFF + r * 33 + q * 4];
            xp[0] = v.x; xp[1] = v.y; xp[2] = v.z; xp[3] = v.w;
        }
        // stage W tile: ws[kk][n], n<256 -> W1[e=n/16, d, h=n%16]; n<304 -> gates
#pragma unroll
        for (int it = 0; it < (KC * NCOLS) / NTHREADS; ++it) {
            int idx = tid + it * NTHREADS;
            int kk = idx / NCOLS;
            int n = idx - kk * NCOLS;
            int d = kc * KC + kk;
            float w;
            if (n < 256) {
                w = W1[(n >> 4) * (DN * H1N) + d * 16 + (n & 15)];
            } else if (n < 304) {
                int m = n - 256;
                w = wgates[(m >> 4) * (DN * EN) + d * 16 + (m & 15)];
            } else {
                w = 0.f;
            }
            sm[WS_OFF + kk * NCOLS + n] = w;
        }
        __syncthreads();

        // logsumexp update (row-per-thread over this chunk)
        if (tid < ROWS) {
            const float* xr = &sm[XS_OFF + tid * 33];
            float cm = xr[0];
#pragma unroll
            for (int kk = 1; kk < KC; ++kk) cm = fmaxf(cm, xr[kk]);
            float nm = fmaxf(lm, cm);
            ls *= __expf(lm - nm);
            float add = 0.f;
#pragma unroll
            for (int kk = 0; kk < KC; ++kk) add += __expf(xr[kk] - nm);
            ls += add;
            lm = nm;
        }

        // f32x2 outer-product GEMM
#pragma unroll 4
        for (int kk = 0; kk < KC; ++kk) {
            unsigned long long a2[4];
#pragma unroll
            for (int i = 0; i < 4; i++) a2[i] = bcast2(sm[XS_OFF + (rbase + i) * 33 + kk]);
#pragma unroll
            for (int j = 0; j < 5; j++) {
                unsigned long long bb =
                    *(const unsigned long long*)&sm[WS_OFF + kk * NCOLS + 2 * (tx + 32 * j)];
#pragma unroll
                for (int i = 0; i < 4; i++) fma2(acc[i][j], a2[i], bb);
            }
        }
        __syncthreads();
    }

    // ---- write accumulators into padded epilogue smem (h1 with bias+relu, logits) ----
#pragma unroll
    for (int j = 0; j < 5; j++) {
        int c = 2 * (tx + 32 * j);
#pragma unroll
        for (int i = 0; i < 4; i++) {
            int row = rbase + i;
            float vx, vy;
            unpack2(acc[i][j], vx, vy);
            if (c < 256) {
                int e = c >> 4, h = c & 15;  // c even -> h<=14, pair stays in-expert
                sm[H1_OFF + row * 273 + e * 17 + h]     = fmaxf(vx + sm[B1_OFF + c], 0.f);
                sm[H1_OFF + row * 273 + e * 17 + h + 1] = fmaxf(vy + sm[B1_OFF + c + 1], 0.f);
            } else if (c < 304) {
                int m = c - 256;
                sm[LG_OFF + row * 49 + m]     = vx + sm[BG_OFF + m];
                sm[LG_OFF + row * 49 + m + 1] = vy + sm[BG_OFF + m + 1];
            }
        }
    }
    if (tid < ROWS) sm[LSE_OFF + tid] = lm + __logf(ls);
    __syncthreads();

    if (tid == 0) {
        float s = 0.f;
        for (int r = 0; r < ROWS; r++) s += sm[LSE_OFF + r];
        atomicAdd(&g_rz, s);
    }

    // ---- gating + sparse expert layers 2/3: one thread per (task,row) ----
    if (tid < ROWS * TT) {
        int t = tid / ROWS;
        int row = tid - t * ROWS;
        float l[16];
#pragma unroll
        for (int e = 0; e < 16; e++) l[e] = sm[LG_OFF + row * 49 + t * 16 + e];
        int sel[4];
        float sv[4];
#pragma unroll
        for (int k = 0; k < 4; k++) {
            float best = -INFINITY;
            int bi = 0;
#pragma unroll
            for (int e = 0; e < 16; e++)
                if (l[e] > best) { best = l[e]; bi = e; }
            sv[k] = best;
            sel[k] = bi;
            l[bi] = -INFINITY;
        }
        float m = sv[0];
        float g[4], ssum = 0.f;
#pragma unroll
        for (int k = 0; k < 4; k++) { g[k] = __expf(sv[k] - m); ssum += g[k]; }
        float inv = 1.f / ssum;

        float y[16];
#pragma unroll
        for (int o = 0; o < 16; o++) y[o] = 0.f;

#pragma unroll
        for (int k = 0; k < 4; k++) {
            int e = sel[k];
            float gk = g[k] * inv;
            float h[16];
#pragma unroll
            for (int i = 0; i < 16; i++) h[i] = sm[H1_OFF + row * 273 + e * 17 + i];
            float h2v[8];
#pragma unroll
            for (int j = 0; j < 8; j++) {
                float a = sm[B2_OFF + e * 9 + j];
#pragma unroll
                for (int i = 0; i < 16; i++) a += h[i] * sm[W2_OFF + e * 130 + i * 8 + j];
                h2v[j] = fmaxf(a, 0.f);
            }
#pragma unroll
            for (int o = 0; o < 16; o++) {
                float a = sm[B3_OFF + e * 17 + o];
#pragma unroll
                for (int j = 0; j < 8; j++) a += h2v[j] * sm[W3_OFF + e * 130 + j * 16 + o];
                y[o] += gk * fmaxf(a, 0.f);
            }
            atomicAdd(&sm[IMP_OFF + t * 16 + e], gk);
            atomicAdd(&sm[LOAD_OFF + t * 16 + e], 1.f);
        }
        float* yo = out + (size_t)t * BN * ON + (size_t)(row0 + row) * ON;
#pragma unroll
        for (int o = 0; o < 16; o++) yo[o] = y[o];
    }
    __syncthreads();

    // flush per-CTA loss partials
    if (tid < 48) atomicAdd(&g_imp[tid], sm[IMP_OFF + tid]);
    else if (tid < 96) atomicAdd(&g_load[tid - 48], sm[LOAD_OFF + tid - 48]);
}

__global__ void moe_finalize_kernel(float* __restrict__ out, int out_size) {
    if (threadIdx.x != 0 || blockIdx.x != 0) return;
    float lb = 0.f;
    for (int t = 0; t < TT; t++) {
        float imp[16], ld[16];
        float si = 0.f, sl = 0.f, sil = 0.f;
        for (int e = 0; e < 16; e++) {
            imp[e] = g_imp[t * 16 + e];
            ld[e]  = g_load[t * 16 + e];
            si += imp[e]; sl += ld[e]; sil += imp[e] * ld[e];
        }
        float mi = si / 16.f, ml = sl / 16.f;
        float vi = 0.f, vl = 0.f;
        for (int e = 0; e < 16; e++) {
            float di = imp[e] - mi, dl = ld[e] - ml;
            vi += di * di; vl += dl * dl;
        }
        vi /= 15.f;  // ddof=1
        vl /= 15.f;
        float cvi = vi / (mi * mi + 1e-10f);
        float cvl = vl / (ml * ml + 1e-10f);
        lb += 0.01f * (cvi + cvl) + 0.01f * 16.f * sil / (float)BN;
    }
    size_t base = (size_t)TT * BN * ON;
    if (out_size > (int)base)     out[base]     = lb;
    if (out_size > (int)base + 1) out[base + 1] = 3.f * 0.001f * g_rz / (float)BN;
}

extern "C" void kernel_launch(void* const* d_in, const int* in_sizes, int n_in,
                              void* d_out, int out_size) {
    const float* x      = (const float*)d_in[0];
    const float* wgates = (const float*)d_in[1];
    const float* bgates = (const float*)d_in[2];
    const float* W1     = (const float*)d_in[3];
    const float* b1     = (const float*)d_in[4];
    const float* W2     = (const float*)d_in[5];
    const float* b2     = (const float*)d_in[6];
    const float* W3     = (const float*)d_in[7];
    const float* b3     = (const float*)d_in[8];
    float* out = (float*)d_out;

    cudaFuncSetAttribute(moe_main_kernel, cudaFuncAttributeMaxDynamicSharedMemorySize,
                         SMEM_FLOATS * sizeof(float));

    moe_init_kernel<<<1, 64>>>();
    moe_main_kernel<<<BN / ROWS, NTHREADS, SMEM_FLOATS * sizeof(float)>>>(
        x, wgates, bgates, W1, b1, W2, b2, W3, b3, out);
    moe_finalize_kernel<<<1, 32>>>(out, out_size);
}